// round 1
// baseline (speedup 1.0000x reference)
#include <cuda_runtime.h>

#define H_IMG 256
#define W_IMG 256
#define B_SZ 8
#define NPIX (B_SZ * H_IMG * W_IMG) /* 524288 */
#define BN_EPS 1e-5f

// -------- scratch (allocation-free: __device__ globals) --------
__device__ float g_y1[B_SZ * 32 * H_IMG * W_IMG];   // conv1 raw output (67 MB)
__device__ float g_y2[B_SZ * 64 * H_IMG * W_IMG];   // conv2 raw output (134 MB)
__device__ float g_w1t[3 * 9 * 32];                 // transposed weights [cin*9][cout]
__device__ float g_w2t[32 * 9 * 64];
__device__ float g_w3t[64 * 9 * 128];
__device__ float g_s1[2 * 32];                      // [sum(32), sumsq(32)]
__device__ float g_s2[2 * 64];
__device__ float g_s3[2 * 128];

__global__ void zero_stats_kernel() {
    int i = threadIdx.x;
    if (i < 64)  g_s1[i] = 0.f;
    if (i < 128) g_s2[i] = 0.f;
    if (i < 256) g_s3[i] = 0.f;
}

// w (OIHW) -> wt[(ci*9+t)*COUT + o]
template <int LAYER>
__global__ void transpose_w_kernel(const float* __restrict__ w) {
    constexpr int CIN  = (LAYER == 1) ? 3  : (LAYER == 2 ? 32 : 64);
    constexpr int COUT = (LAYER == 1) ? 32 : (LAYER == 2 ? 64 : 128);
    float* wt = (LAYER == 1) ? g_w1t : (LAYER == 2 ? g_w2t : g_w3t);
    int idx = blockIdx.x * blockDim.x + threadIdx.x;
    if (idx >= CIN * 9 * COUT) return;
    int o = idx % COUT;
    int r = idx / COUT;       // ci*9 + t
    int ci = r / 9, t = r % 9;
    wt[idx] = w[(o * CIN + ci) * 9 + t];
}

// Direct tiled conv: 16x16 spatial tile, 32 couts per block, CIN chunked in smem.
// Applies BN+leakyReLU of the previous layer on load (padding = 0 post-activation).
// Accumulates per-channel sum / sumsq of (conv + bias) into out_stats.
template <int LAYER, int CIN, int CHUNK, int COUT, bool HAS_BN, bool WRITE>
__global__ __launch_bounds__(256) void conv_kernel(
    const float* __restrict__ image,      // only used when LAYER==1
    const float* __restrict__ in_gamma,   // BN params of previous layer
    const float* __restrict__ in_beta,
    const float* __restrict__ bias)       // this layer's conv bias
{
    const float* in = (LAYER == 1) ? image
                    : (LAYER == 2) ? (const float*)g_y1 : (const float*)g_y2;
    const float* wt = (LAYER == 1) ? (const float*)g_w1t
                    : (LAYER == 2) ? (const float*)g_w2t : (const float*)g_w3t;
    const float* in_stats = (LAYER == 2) ? (const float*)g_s1 : (const float*)g_s2;
    float* out       = (LAYER == 1) ? (float*)g_y1 : (float*)g_y2;
    float* out_stats = (LAYER == 1) ? g_s1 : (LAYER == 2 ? g_s2 : g_s3);

    constexpr int NG = COUT / 32;
    const int tx = threadIdx.x & 15;
    const int ty = threadIdx.x >> 4;
    const int tile_x = blockIdx.x * 16;
    const int tile_y = blockIdx.y * 16;
    const int g = blockIdx.z % NG;
    const int b = blockIdx.z / NG;

    __shared__ float s_in[CHUNK][18][18];
    __shared__ float s_w[CHUNK * 9 * 32];
    __shared__ float s_scale[CHUNK], s_shift[CHUNK];

    float acc[32];
#pragma unroll
    for (int o = 0; o < 32; o++) acc[o] = 0.f;

    for (int c0 = 0; c0 < CIN; c0 += CHUNK) {
        __syncthreads();   // protect previous iteration's smem reads
        if (HAS_BN) {
            if (threadIdx.x < CHUNK) {
                int c = c0 + threadIdx.x;
                float mean = in_stats[c] * (1.f / NPIX);
                float var  = in_stats[CIN + c] * (1.f / NPIX) - mean * mean;
                float is   = rsqrtf(var + BN_EPS);
                float sc   = in_gamma[c] * is;
                s_scale[threadIdx.x] = sc;
                s_shift[threadIdx.x] = in_beta[c] - mean * sc;
            }
            __syncthreads();
        }
        // input tile: (CHUNK)x18x18, zero padded, BN+lrelu applied in-range
        for (int i = threadIdx.x; i < CHUNK * 18 * 18; i += 256) {
            int c  = i / 324;
            int r  = i - c * 324;
            int yy = r / 18;
            int xx = r - yy * 18;
            int gy = tile_y + yy - 1, gx = tile_x + xx - 1;
            float v = 0.f;
            if (gy >= 0 && gy < H_IMG && gx >= 0 && gx < W_IMG) {
                v = in[((b * CIN + c0 + c) * H_IMG + gy) * W_IMG + gx];
                if (HAS_BN) {
                    v = v * s_scale[c] + s_shift[c];
                    v = v > 0.f ? v : 0.01f * v;
                }
            }
            s_in[c][yy][xx] = v;
        }
        // weights: coalesced global (runs of 32 couts) + conflict-free smem store
        for (int i = threadIdx.x; i < CHUNK * 9 * 32; i += 256) {
            int rt = i >> 5;   // c*9 + t (relative)
            int o  = i & 31;
            s_w[i] = wt[(c0 * 9 + rt) * COUT + g * 32 + o];
        }
        __syncthreads();

#pragma unroll 1
        for (int c = 0; c < CHUNK; c++) {
#pragma unroll
            for (int t = 0; t < 9; t++) {
                float x = s_in[c][ty + t / 3][tx + t % 3];
                const float4* wv = (const float4*)&s_w[(c * 9 + t) * 32];
#pragma unroll
                for (int o4 = 0; o4 < 8; o4++) {
                    float4 w4 = wv[o4];
                    acc[o4 * 4 + 0] = fmaf(x, w4.x, acc[o4 * 4 + 0]);
                    acc[o4 * 4 + 1] = fmaf(x, w4.y, acc[o4 * 4 + 1]);
                    acc[o4 * 4 + 2] = fmaf(x, w4.z, acc[o4 * 4 + 2]);
                    acc[o4 * 4 + 3] = fmaf(x, w4.w, acc[o4 * 4 + 3]);
                }
            }
        }
    }

#pragma unroll
    for (int o = 0; o < 32; o++) acc[o] += bias[g * 32 + o];

    if (WRITE) {
        int gy = tile_y + ty, gx = tile_x + tx;
        int base = ((b * COUT + g * 32) * H_IMG + gy) * W_IMG + gx;
#pragma unroll
        for (int o = 0; o < 32; o++) out[base + o * (H_IMG * W_IMG)] = acc[o];
    }

    // per-channel sum / sumsq: warp shuffle reduce, one atomic per warp per channel
    int lane = threadIdx.x & 31;
#pragma unroll
    for (int o = 0; o < 32; o++) {
        float v = acc[o];
        float v2 = v * v;
#pragma unroll
        for (int s = 16; s > 0; s >>= 1) {
            v  += __shfl_down_sync(0xffffffffu, v, s);
            v2 += __shfl_down_sync(0xffffffffu, v2, s);
        }
        if (lane == 0) {
            atomicAdd(&out_stats[g * 32 + o], v);
            atomicAdd(&out_stats[COUT + g * 32 + o], v2);
        }
    }
}

// Gather the three 7x7 patch sets (exact pixel copies). Output order:
// anchors [0,1176) | positives [1176,2352) | negatives [2352,3528)
__global__ void patch_kernel(const float* __restrict__ image,
                             const int* __restrict__ a_xy,
                             const int* __restrict__ p_xy,
                             const int* __restrict__ n_xy,
                             float* __restrict__ out)
{
    int idx = blockIdx.x * blockDim.x + threadIdx.x;
    if (idx >= 3 * B_SZ * 3 * 7 * 7) return;
    int which = idx / 1176;
    int r  = idx % 1176;
    int b  = r / 147;
    int r2 = r % 147;
    int c  = r2 / 49;
    int p  = r2 % 49;
    int dy = p / 7, dx = p % 7;
    const int* xy = (which == 0) ? a_xy : (which == 1 ? p_xy : n_xy);
    int row = xy[b * 64 + 62];   // [:, -1, 0]  (last of 32 patches)
    int col = xy[b * 64 + 63];   // [:, -1, 1]
    out[idx] = image[((b * 3 + c) * H_IMG + (row - 3 + dy)) * W_IMG + (col - 3 + dx)];
}

// Recompute z3 at the 8 gather points (reference uses n_xy here), apply BN3+lrelu.
__global__ void encode_kernel(const int* __restrict__ n_xy,
                              const float* __restrict__ bn2_g, const float* __restrict__ bn2_b,
                              const float* __restrict__ conv3_b,
                              const float* __restrict__ bn3_g, const float* __restrict__ bn3_b,
                              float* __restrict__ out)
{
    int b = blockIdx.x;
    int o = threadIdx.x;   // 128 threads = 128 output channels
    __shared__ float s_z2[64 * 9];
    int row = n_xy[b * 64 + 62];
    int col = n_xy[b * 64 + 63];
    // coords are in [3,252] -> the 3x3 neighborhood is interior, no padding needed
    for (int i = threadIdx.x; i < 576; i += 128) {
        int c = i / 9, p = i % 9;
        int ky = p / 3 - 1, kx = p % 3 - 1;
        float mean = g_s2[c] * (1.f / NPIX);
        float var  = g_s2[64 + c] * (1.f / NPIX) - mean * mean;
        float is   = rsqrtf(var + BN_EPS);
        float sc   = bn2_g[c] * is;
        float sh   = bn2_b[c] - mean * sc;
        float v = g_y2[((b * 64 + c) * H_IMG + row + ky) * W_IMG + col + kx];
        v = v * sc + sh;
        v = v > 0.f ? v : 0.01f * v;
        s_z2[i] = v;
    }
    __syncthreads();
    float acc = conv3_b[o];
    for (int i = 0; i < 576; i++)
        acc = fmaf(s_z2[i], g_w3t[i * 128 + o], acc);
    float mean = g_s3[o] * (1.f / NPIX);
    float var  = g_s3[128 + o] * (1.f / NPIX) - mean * mean;
    float is   = rsqrtf(var + BN_EPS);
    float v = (acc - mean) * is * bn3_g[o] + bn3_b[o];
    v = v > 0.f ? v : 0.01f * v;
    out[3528 + b * 128 + o] = v;
}

extern "C" void kernel_launch(void* const* d_in, const int* in_sizes, int n_in,
                              void* d_out, int out_size) {
    const float* image = (const float*)d_in[0];
    const int*   a_xy  = (const int*)d_in[1];
    const int*   p_xy  = (const int*)d_in[2];
    const int*   n_xy  = (const int*)d_in[3];
    const float* w1  = (const float*)d_in[4];
    const float* b1  = (const float*)d_in[5];
    const float* g1  = (const float*)d_in[6];
    const float* be1 = (const float*)d_in[7];
    const float* w2  = (const float*)d_in[8];
    const float* b2  = (const float*)d_in[9];
    const float* g2  = (const float*)d_in[10];
    const float* be2 = (const float*)d_in[11];
    const float* w3  = (const float*)d_in[12];
    const float* b3  = (const float*)d_in[13];
    const float* g3  = (const float*)d_in[14];
    const float* be3 = (const float*)d_in[15];
    // d_in[16]=recon_w, d_in[17]=recon_b : dead in the reference, unused.
    float* out = (float*)d_out;

    zero_stats_kernel<<<1, 256>>>();
    transpose_w_kernel<1><<<(3 * 9 * 32 + 255) / 256, 256>>>(w1);
    transpose_w_kernel<2><<<(32 * 9 * 64 + 255) / 256, 256>>>(w2);
    transpose_w_kernel<3><<<(64 * 9 * 128 + 255) / 256, 256>>>(w3);

    conv_kernel<1, 3, 3, 32, false, true><<<dim3(16, 16, 8), 256>>>(image, nullptr, nullptr, b1);
    conv_kernel<2, 32, 8, 64, true, true><<<dim3(16, 16, 16), 256>>>(nullptr, g1, be1, b2);
    conv_kernel<3, 64, 8, 128, true, false><<<dim3(16, 16, 32), 256>>>(nullptr, g2, be2, b3);

    patch_kernel<<<14, 256>>>(image, a_xy, p_xy, n_xy, out);
    encode_kernel<<<8, 128>>>(n_xy, g2, be2, b3, g3, be3, out);
}